// round 4
// baseline (speedup 1.0000x reference)
#include <cuda_runtime.h>
#include <cstdint>

#define NN 100000
#define NEDGE 1600000
#define SCAN_BS 512
#define NSCAN_BLOCKS ((NN + SCAN_BS - 1) / SCAN_BS)   // 196

// ---------------- device scratch (no allocation; referenced by name only) --
__device__ int   g_is64;
__device__ int   g_rows[NEDGE];
__device__ int   g_cols[NEDGE];
__device__ float g_dinv[NN];
__device__ int   g_cnt[NN];
__device__ int   g_rowptr[NN];
__device__ int   g_cursor[NN];
__device__ int   g_colidx[NEDGE];
__device__ int   g_bsum[NSCAN_BLOCKS];
__device__ int   g_boff[NSCAN_BLOCKS];
__device__ __align__(16) float g_bufA[(size_t)NN * 128];
__device__ __align__(16) float g_bufB[(size_t)NN * 128];

__device__ __forceinline__ float* buf_sel(int s) {
    return s == 0 ? g_bufA : g_bufB;
}

// ---------------- edge dtype detection + extraction ----------------
// If edge_index survived as int64: every (lo,hi) int32 pair has hi==0 and
// lo in [0,NN). If it was downcast to int32, "hi" is a random index and is
// nonzero with P ~ (1 - 1e-5) per sample -> 1024 samples decide exactly.
__global__ void k_detect(const int* __restrict__ ei) {
    __shared__ int bad;
    if (threadIdx.x == 0) bad = 0;
    __syncthreads();
    for (int k = threadIdx.x; k < 1024; k += blockDim.x) {
        int lo = ei[2 * k], hi = ei[2 * k + 1];
        if (hi != 0 || lo < 0 || lo >= NN) bad = 1;
    }
    __syncthreads();
    if (threadIdx.x == 0) g_is64 = (bad == 0) ? 1 : 0;
}

__global__ void k_extract(const int* __restrict__ ei) {
    int e = blockIdx.x * blockDim.x + threadIdx.x;
    if (e >= NEDGE) return;
    int r, c;
    if (g_is64) {
        r = ei[2 * e];                    // lo word of rows[e]
        c = ei[2 * (NEDGE + e)];          // lo word of cols[e]
    } else {
        r = ei[e];
        c = ei[NEDGE + e];
    }
    // safety clamp: a bad index becomes a wrong answer, not a trap
    r = min(max(r, 0), NN - 1);
    c = min(max(c, 0), NN - 1);
    g_rows[e] = r;
    g_cols[e] = c;
}

// ---------------- degree / CSR build ----------------
__global__ void k_cnt_zero() {
    int i = blockIdx.x * blockDim.x + threadIdx.x;
    if (i < NN) { g_cnt[i] = 0; g_cursor[i] = 0; }
}

__global__ void k_cnt() {
    int e = blockIdx.x * blockDim.x + threadIdx.x;
    if (e < NEDGE) atomicAdd(&g_cnt[g_rows[e]], 1);
}

__global__ void k_dinv() {
    int i = blockIdx.x * blockDim.x + threadIdx.x;
    if (i < NN) g_dinv[i] = rsqrtf(1.0f + (float)g_cnt[i]);
}

// scan phase A: per-block sums of cnt
__global__ void k_scanA() {
    __shared__ int sh[SCAN_BS];
    int i = blockIdx.x * SCAN_BS + threadIdx.x;
    sh[threadIdx.x] = (i < NN) ? g_cnt[i] : 0;
    __syncthreads();
    for (int s = SCAN_BS / 2; s > 0; s >>= 1) {
        if (threadIdx.x < s) sh[threadIdx.x] += sh[threadIdx.x + s];
        __syncthreads();
    }
    if (threadIdx.x == 0) g_bsum[blockIdx.x] = sh[0];
}

// scan phase B: exclusive scan of 196 block sums
__global__ void k_scanB() {
    if (threadIdx.x == 0 && blockIdx.x == 0) {
        int acc = 0;
        for (int b = 0; b < NSCAN_BLOCKS; b++) {
            g_boff[b] = acc;
            acc += g_bsum[b];
        }
    }
}

// scan phase C: intra-block exclusive scan + block offset -> rowptr
__global__ void k_scanC() {
    __shared__ int sh[SCAN_BS];
    int i = blockIdx.x * SCAN_BS + threadIdx.x;
    int v = (i < NN) ? g_cnt[i] : 0;
    sh[threadIdx.x] = v;
    __syncthreads();
    for (int s = 1; s < SCAN_BS; s <<= 1) {
        int add = (threadIdx.x >= s) ? sh[threadIdx.x - s] : 0;
        __syncthreads();
        sh[threadIdx.x] += add;
        __syncthreads();
    }
    if (i < NN) g_rowptr[i] = g_boff[blockIdx.x] + sh[threadIdx.x] - v;
}

__global__ void k_fill() {
    int e = blockIdx.x * blockDim.x + threadIdx.x;
    if (e >= NEDGE) return;
    int r = g_rows[e];
    int pos = g_rowptr[r] + atomicAdd(&g_cursor[r], 1);
    g_colidx[pos] = g_cols[e];
}

// ---------------- GEMM: C[NN x K] = A[NN x 128] @ W[128 x K] ----------------
// A = Aext ? Aext : buf_sel(src);  C = buf_sel(dst).
// 256 threads, 32 rows/block, 64-col tiles, 8 rows x 1 col per thread.
template <int K>
__global__ void k_gemm(const float* __restrict__ Aext, int src, int dst,
                       const float* __restrict__ W) {
    __shared__ float As[32][128];
    __shared__ float Ws[128][64];
    const float* A = Aext ? Aext : buf_sel(src);
    float* C = buf_sel(dst);
    const int tid = threadIdx.x;
    const int row0 = blockIdx.x * 32;

    const float4* A4 = (const float4*)(A + (size_t)row0 * 128);
    float4* As4 = (float4*)&As[0][0];
#pragma unroll
    for (int i = 0; i < 4; i++) As4[tid + i * 256] = A4[tid + i * 256];

    const int c = tid & 63;
    const int r0 = tid >> 6;  // 0..3

#pragma unroll
    for (int ct = 0; ct < K / 64; ct++) {
        __syncthreads();
        for (int i = tid; i < 128 * 64; i += 256) {
            int m = i >> 6, cc = i & 63;
            Ws[m][cc] = W[m * K + ct * 64 + cc];
        }
        __syncthreads();

        float acc[8];
#pragma unroll
        for (int r = 0; r < 8; r++) acc[r] = 0.0f;

#pragma unroll
        for (int m = 0; m < 128; m += 4) {
            float4 a[8];
#pragma unroll
            for (int r = 0; r < 8; r++)
                a[r] = *(const float4*)&As[r0 + r * 4][m];
#pragma unroll
            for (int mm = 0; mm < 4; mm++) {
                float w = Ws[m + mm][c];
#pragma unroll
                for (int r = 0; r < 8; r++)
                    acc[r] += ((const float*)&a[r])[mm] * w;
            }
        }
#pragma unroll
        for (int r = 0; r < 8; r++)
            C[(size_t)(row0 + r0 + r * 4) * K + ct * 64 + c] = acc[r];
    }
}

// ---------------- SPMM gather (CSR), warp per row, fused bias(+relu) -------
// H = buf_sel(src);  out = Oext ? Oext : buf_sel(dst).
// out[r,:] = act( dinv[r]^2*H[r,:] + sum_c dinv[r]*dinv[c]*H[c,:] + bias )
template <int K, bool RELU>
__global__ void k_spmm_gather(int src, const float* __restrict__ bias,
                              float* __restrict__ Oext, int dst) {
    const int warp = threadIdx.x >> 5;
    const int lane = threadIdx.x & 31;
    const int row = blockIdx.x * 8 + warp;
    if (row >= NN) return;

    const float* H = buf_sel(src);
    float* out = Oext ? Oext : buf_sel(dst);

    constexpr int L = K / 4;  // float4 lanes used (32 for K=128, 16 for K=64)
    const float dr = g_dinv[row];
    const int beg = g_rowptr[row];
    const int n = g_cnt[row];

    float4 acc = make_float4(0.f, 0.f, 0.f, 0.f);
    if (lane < L) {
        float4 h = ((const float4*)H)[(size_t)row * L + lane];
        float w = dr * dr;
        acc.x = w * h.x; acc.y = w * h.y; acc.z = w * h.z; acc.w = w * h.w;
    }
    for (int k = 0; k < n; k++) {
        int c = __ldg(&g_colidx[beg + k]);  // warp-uniform broadcast load
        float w = dr * g_dinv[c];
        if (lane < L) {
            float4 v = ((const float4*)H)[(size_t)c * L + lane];
            acc.x += w * v.x; acc.y += w * v.y; acc.z += w * v.z; acc.w += w * v.w;
        }
    }
    if (lane < L) {
        float4 b = ((const float4*)bias)[lane];
        acc.x += b.x; acc.y += b.y; acc.z += b.z; acc.w += b.w;
        if (RELU) {
            acc.x = fmaxf(acc.x, 0.0f); acc.y = fmaxf(acc.y, 0.0f);
            acc.z = fmaxf(acc.z, 0.0f); acc.w = fmaxf(acc.w, 0.0f);
        }
        ((float4*)out)[(size_t)row * L + lane] = acc;
    }
}

// ---------------- launch ----------------
extern "C" void kernel_launch(void* const* d_in, const int* in_sizes, int n_in,
                              void* d_out, int out_size) {
    const float* x = (const float*)d_in[0];
    const int* ei = (const int*)d_in[1];   // edge_index, dtype auto-detected
    const float* W0 = (const float*)d_in[2];
    const float* b0 = (const float*)d_in[3];
    const float* W1 = (const float*)d_in[4];
    const float* b1 = (const float*)d_in[5];
    const float* W2 = (const float*)d_in[6];
    const float* b2 = (const float*)d_in[7];
    float* out = (float*)d_out;

    const int TB = 256;
    const int gN = (NN + TB - 1) / TB;
    const int gE = (NEDGE + TB - 1) / TB;
    const int gGemm = NN / 32;
    const int gSpmm = (NN + 7) / 8;   // 8 warps (rows) per block

    // ---- edge ingest (dtype-robust) ----
    k_detect<<<1, 256>>>(ei);
    k_extract<<<gE, TB>>>(ei);

    // ---- CSR build + normalization ----
    k_cnt_zero<<<gN, TB>>>();
    k_cnt<<<gE, TB>>>();
    k_dinv<<<gN, TB>>>();
    k_scanA<<<NSCAN_BLOCKS, SCAN_BS>>>();
    k_scanB<<<1, 32>>>();
    k_scanC<<<NSCAN_BLOCKS, SCAN_BS>>>();
    k_fill<<<gE, TB>>>();

    // ---- layer 1: h = relu(spmm(x @ W0) + b0)   (x -> bufA -> bufB) ----
    k_gemm<128><<<gGemm, TB>>>(x, -1, 0, W0);
    k_spmm_gather<128, true><<<gSpmm, TB>>>(0, b0, nullptr, 1);
    // ---- layer 2: h = relu(spmm(h @ W1) + b1)   (bufB -> bufA -> bufB) ----
    k_gemm<128><<<gGemm, TB>>>(nullptr, 1, 0, W1);
    k_spmm_gather<128, true><<<gSpmm, TB>>>(0, b1, nullptr, 1);
    // ---- layer 3: out = spmm(h @ W2) + b2       (bufB -> bufA -> out) ----
    k_gemm<64><<<gGemm, TB>>>(nullptr, 1, 0, W2);
    k_spmm_gather<64, false><<<gSpmm, TB>>>(0, b2, out, -1);
}

// round 5
// speedup vs baseline: 1.0407x; 1.0407x over previous
#include <cuda_runtime.h>
#include <cstdint>

#define NN 100000
#define NEDGE 1600000
#define SCAN_BS 512
#define NSCAN_BLOCKS ((NN + SCAN_BS - 1) / SCAN_BS)   // 196

// ---------------- device scratch (no allocation; referenced by name only) --
__device__ int   g_is64;
__device__ int   g_rows[NEDGE];
__device__ int   g_cols[NEDGE];
__device__ float g_dinv[NN];
__device__ int   g_cnt[NN];
__device__ int   g_rowptr[NN];
__device__ int   g_cursor[NN];
__device__ int   g_colidx[NEDGE];
__device__ int   g_bsum[NSCAN_BLOCKS];
__device__ int   g_boff[NSCAN_BLOCKS];
__device__ __align__(16) float g_bufA[(size_t)NN * 128];
__device__ __align__(16) float g_bufB[(size_t)NN * 128];

__device__ __forceinline__ float* buf_sel(int s) {
    return s == 0 ? g_bufA : g_bufB;
}

// ---------------- packed f32x2 helpers (Blackwell FFMA2) ----------------
__device__ __forceinline__ unsigned long long pack2(float lo, float hi) {
    unsigned long long r;
    asm("mov.b64 %0, {%1, %2};" : "=l"(r) : "f"(lo), "f"(hi));
    return r;
}
__device__ __forceinline__ unsigned long long fma2(unsigned long long a,
                                                   unsigned long long b,
                                                   unsigned long long c) {
    unsigned long long d;
    asm("fma.rn.f32x2 %0, %1, %2, %3;" : "=l"(d) : "l"(a), "l"(b), "l"(c));
    return d;
}
__device__ __forceinline__ void unpack2(unsigned long long v, float& lo, float& hi) {
    asm("mov.b64 {%0, %1}, %2;" : "=f"(lo), "=f"(hi) : "l"(v));
}

// ---------------- edge dtype detection + extraction (+degree count) --------
__global__ void k_detect(const int* __restrict__ ei) {
    __shared__ int bad;
    if (threadIdx.x == 0) bad = 0;
    __syncthreads();
    for (int k = threadIdx.x; k < 1024; k += blockDim.x) {
        int lo = ei[2 * k], hi = ei[2 * k + 1];
        if (hi != 0 || lo < 0 || lo >= NN) bad = 1;
    }
    __syncthreads();
    if (threadIdx.x == 0) g_is64 = (bad == 0) ? 1 : 0;
}

__global__ void k_cnt_zero() {
    int i = blockIdx.x * blockDim.x + threadIdx.x;
    if (i < NN) { g_cnt[i] = 0; g_cursor[i] = 0; }
}

// extract indices (int64 or int32 source) + count degrees in one pass
__global__ void k_extract(const int* __restrict__ ei) {
    int e = blockIdx.x * blockDim.x + threadIdx.x;
    if (e >= NEDGE) return;
    int r, c;
    if (g_is64) {
        r = ei[2 * e];
        c = ei[2 * (NEDGE + e)];
    } else {
        r = ei[e];
        c = ei[NEDGE + e];
    }
    r = min(max(r, 0), NN - 1);
    c = min(max(c, 0), NN - 1);
    g_rows[e] = r;
    g_cols[e] = c;
    atomicAdd(&g_cnt[r], 1);
}

__global__ void k_dinv() {
    int i = blockIdx.x * blockDim.x + threadIdx.x;
    if (i < NN) g_dinv[i] = rsqrtf(1.0f + (float)g_cnt[i]);
}

// scan phase A: per-block sums of cnt
__global__ void k_scanA() {
    __shared__ int sh[SCAN_BS];
    int i = blockIdx.x * SCAN_BS + threadIdx.x;
    sh[threadIdx.x] = (i < NN) ? g_cnt[i] : 0;
    __syncthreads();
    for (int s = SCAN_BS / 2; s > 0; s >>= 1) {
        if (threadIdx.x < s) sh[threadIdx.x] += sh[threadIdx.x + s];
        __syncthreads();
    }
    if (threadIdx.x == 0) g_bsum[blockIdx.x] = sh[0];
}

// scan phase B: exclusive scan of 196 block sums
__global__ void k_scanB() {
    if (threadIdx.x == 0 && blockIdx.x == 0) {
        int acc = 0;
        for (int b = 0; b < NSCAN_BLOCKS; b++) {
            g_boff[b] = acc;
            acc += g_bsum[b];
        }
    }
}

// scan phase C: intra-block exclusive scan + block offset -> rowptr
__global__ void k_scanC() {
    __shared__ int sh[SCAN_BS];
    int i = blockIdx.x * SCAN_BS + threadIdx.x;
    int v = (i < NN) ? g_cnt[i] : 0;
    sh[threadIdx.x] = v;
    __syncthreads();
    for (int s = 1; s < SCAN_BS; s <<= 1) {
        int add = (threadIdx.x >= s) ? sh[threadIdx.x - s] : 0;
        __syncthreads();
        sh[threadIdx.x] += add;
        __syncthreads();
    }
    if (i < NN) g_rowptr[i] = g_boff[blockIdx.x] + sh[threadIdx.x] - v;
}

__global__ void k_fill() {
    int e = blockIdx.x * blockDim.x + threadIdx.x;
    if (e >= NEDGE) return;
    int r = g_rows[e];
    int pos = g_rowptr[r] + atomicAdd(&g_cursor[r], 1);
    g_colidx[pos] = g_cols[e];
}

// ---------------- GEMM via packed f32x2: C[NN x K] = A[NN x 128] @ W[128 x K]
// 128 threads/block, tile 32 rows x 64 cols, each thread 8 rows x 2 cols.
// AsD: A tile pre-duplicated {a,a} u64 [32][128] (32KB).  Ws: [128][64] (32KB).
// Dynamic smem 64KB -> 3 blocks/SM. Inner loop: 8 FFMA2 + 9 LDS.64 per k.
template <int K>
__global__ void k_gemm2(const float* __restrict__ Aext, int src, int dst,
                        const float* __restrict__ W) {
    extern __shared__ char smem_raw[];
    unsigned long long* AsD = (unsigned long long*)smem_raw;          // [32][128]
    float* Ws = (float*)(smem_raw + 32 * 128 * 8);                    // [128][64]

    const float* A = Aext ? Aext : buf_sel(src);
    float* C = buf_sel(dst);
    const int tid = threadIdx.x;            // 128 threads
    const int row0 = blockIdx.x * 32;
    const int cp = tid & 31;                // column pair (cols 2cp, 2cp+1)
    const int g = tid >> 5;                 // row group (rows g*8 .. g*8+7)

    // Load A tile, duplicated: scalar loads (coalesced), STS.64 conflict-free.
#pragma unroll
    for (int i = 0; i < 32; i++) {
        int idx = tid + i * 128;            // 0..4095
        int r = idx >> 7, kk = idx & 127;
        float v = A[(size_t)(row0 + r) * 128 + kk];
        AsD[r * 128 + kk] = pack2(v, v);
    }

    const unsigned long long* AsRow = AsD + (g * 8) * 128;

#pragma unroll
    for (int ct = 0; ct < K / 64; ct++) {
        __syncthreads();
        // Load Ws tile: 128x64 floats = 2048 float4, 16 per thread.
#pragma unroll
        for (int i = 0; i < 16; i++) {
            int idx = tid + i * 128;        // float4 index 0..2047
            int m = idx >> 4, q = idx & 15;
            float4 v = *(const float4*)(W + (size_t)m * K + ct * 64 + 4 * q);
            *(float4*)(Ws + m * 64 + 4 * q) = v;
        }
        __syncthreads();

        unsigned long long acc[8];
#pragma unroll
        for (int r = 0; r < 8; r++) acc[r] = 0ULL;

#pragma unroll 4
        for (int m = 0; m < 128; m++) {
            unsigned long long w2 = *(const unsigned long long*)(Ws + m * 64 + 2 * cp);
#pragma unroll
            for (int r = 0; r < 8; r++)
                acc[r] = fma2(AsRow[r * 128 + m], w2, acc[r]);
        }

#pragma unroll
        for (int r = 0; r < 8; r++) {
            float lo, hi;
            unpack2(acc[r], lo, hi);
            *(float2*)&C[(size_t)(row0 + g * 8 + r) * K + ct * 64 + 2 * cp] =
                make_float2(lo, hi);
        }
    }
}

// ---------------- SPMM gather (CSR), fused bias(+relu) ---------------------
// K=128: warp per row (32 float4 lanes). K=64: 2 rows per warp (16 lanes each).
// out[r,:] = act( dinv[r]^2*H[r,:] + sum_c dinv[r]*dinv[c]*H[c,:] + bias )
template <int K, bool RELU>
__global__ void k_spmm_gather(int src, const float* __restrict__ bias,
                              float* __restrict__ Oext, int dst) {
    constexpr int L = K / 4;            // float4 lanes per row (32 or 16)
    constexpr int RPW = 32 / L;         // rows per warp (1 or 2)
    const int warp = threadIdx.x >> 5;
    const int lane = threadIdx.x & 31;
    const int sub = lane / L;
    const int ll = lane % L;
    const int row = (blockIdx.x * 8 + warp) * RPW + sub;
    if (row >= NN) return;

    const float* H = buf_sel(src);
    const float4* H4 = (const float4*)H;
    float* out = Oext ? Oext : buf_sel(dst);

    const float dr = g_dinv[row];
    const int beg = g_rowptr[row];
    const int n = g_cnt[row];

    float4 h = H4[(size_t)row * L + ll];
    float wss = dr * dr;
    float4 acc = make_float4(wss * h.x, wss * h.y, wss * h.z, wss * h.w);

    int k = 0;
    const int n4 = n & ~3;
    for (; k < n4; k += 4) {
        int c0 = __ldg(&g_colidx[beg + k + 0]);
        int c1 = __ldg(&g_colidx[beg + k + 1]);
        int c2 = __ldg(&g_colidx[beg + k + 2]);
        int c3 = __ldg(&g_colidx[beg + k + 3]);
        float w0 = dr * g_dinv[c0];
        float w1 = dr * g_dinv[c1];
        float w2 = dr * g_dinv[c2];
        float w3 = dr * g_dinv[c3];
        float4 v0 = H4[(size_t)c0 * L + ll];
        float4 v1 = H4[(size_t)c1 * L + ll];
        float4 v2 = H4[(size_t)c2 * L + ll];
        float4 v3 = H4[(size_t)c3 * L + ll];
        acc.x += w0 * v0.x; acc.y += w0 * v0.y; acc.z += w0 * v0.z; acc.w += w0 * v0.w;
        acc.x += w1 * v1.x; acc.y += w1 * v1.y; acc.z += w1 * v1.z; acc.w += w1 * v1.w;
        acc.x += w2 * v2.x; acc.y += w2 * v2.y; acc.z += w2 * v2.z; acc.w += w2 * v2.w;
        acc.x += w3 * v3.x; acc.y += w3 * v3.y; acc.z += w3 * v3.z; acc.w += w3 * v3.w;
    }
    for (; k < n; k++) {
        int c = __ldg(&g_colidx[beg + k]);
        float w = dr * g_dinv[c];
        float4 v = H4[(size_t)c * L + ll];
        acc.x += w * v.x; acc.y += w * v.y; acc.z += w * v.z; acc.w += w * v.w;
    }

    float4 b = ((const float4*)bias)[ll];
    acc.x += b.x; acc.y += b.y; acc.z += b.z; acc.w += b.w;
    if (RELU) {
        acc.x = fmaxf(acc.x, 0.0f); acc.y = fmaxf(acc.y, 0.0f);
        acc.z = fmaxf(acc.z, 0.0f); acc.w = fmaxf(acc.w, 0.0f);
    }
    ((float4*)out)[(size_t)row * L + ll] = acc;
}

// ---------------- launch ----------------
extern "C" void kernel_launch(void* const* d_in, const int* in_sizes, int n_in,
                              void* d_out, int out_size) {
    const float* x = (const float*)d_in[0];
    const int* ei = (const int*)d_in[1];
    const float* W0 = (const float*)d_in[2];
    const float* b0 = (const float*)d_in[3];
    const float* W1 = (const float*)d_in[4];
    const float* b1 = (const float*)d_in[5];
    const float* W2 = (const float*)d_in[6];
    const float* b2 = (const float*)d_in[7];
    float* out = (float*)d_out;

    const int TB = 256;
    const int gN = (NN + TB - 1) / TB;
    const int gE = (NEDGE + TB - 1) / TB;
    const int gGemm = NN / 32;                       // 3125
    const int gSpmm128 = (NN + 7) / 8;               // 1 row/warp
    const int gSpmm64 = (NN + 15) / 16;              // 2 rows/warp
    const int GEMM_SMEM = 64 * 1024;

    static bool attr_set = false;
    if (!attr_set) {
        cudaFuncSetAttribute(k_gemm2<128>, cudaFuncAttributeMaxDynamicSharedMemorySize, GEMM_SMEM);
        cudaFuncSetAttribute(k_gemm2<64>, cudaFuncAttributeMaxDynamicSharedMemorySize, GEMM_SMEM);
        attr_set = true;
    }

    // ---- edge ingest + CSR build ----
    k_detect<<<1, 256>>>(ei);
    k_cnt_zero<<<gN, TB>>>();
    k_extract<<<gE, TB>>>(ei);
    k_dinv<<<gN, TB>>>();
    k_scanA<<<NSCAN_BLOCKS, SCAN_BS>>>();
    k_scanB<<<1, 32>>>();
    k_scanC<<<NSCAN_BLOCKS, SCAN_BS>>>();
    k_fill<<<gE, TB>>>();

    // ---- layer 1: h = relu(spmm(x @ W0) + b0)   (x -> bufA -> bufB) ----
    k_gemm2<128><<<gGemm, 128, GEMM_SMEM>>>(x, -1, 0, W0);
    k_spmm_gather<128, true><<<gSpmm128, TB>>>(0, b0, nullptr, 1);
    // ---- layer 2 ----
    k_gemm2<128><<<gGemm, 128, GEMM_SMEM>>>(nullptr, 1, 0, W1);
    k_spmm_gather<128, true><<<gSpmm128, TB>>>(0, b1, nullptr, 1);
    // ---- layer 3 ----
    k_gemm2<64><<<gGemm, 128, GEMM_SMEM>>>(nullptr, 1, 0, W2);
    k_spmm_gather<64, false><<<gSpmm64, TB>>>(0, b2, out, -1);
}